// round 6
// baseline (speedup 1.0000x reference)
#include <cuda_runtime.h>
#include <cuda_bf16.h>
#include <cstdint>

#define DINLINE __device__ __forceinline__

// ---------------- problem constants ----------------
static constexpr int C_DIM   = 256;    // feature dim
static constexpr int K_G     = 1024;   // number of graph embeddings
static constexpr int TILE_M  = 128;    // local rows per CTA (== num_assign)
static constexpr int NB      = 1024;   // number of CTAs / batches
static constexpr int CHUNK_N = 128;    // g rows per chunk
static constexpr int NCHUNK  = K_G / CHUNK_N;   // 8
static constexpr int NKSTEP  = C_DIM / 16;      // 16 k-steps of k=16
static constexpr int NTHREADS = 512;   // 16 warps

// ---------------- smem layout (dynamic) ----------------
static constexpr int SM_SCALE = 0;                  // 128 floats: sumsq -> scale
static constexpr int SM_POS   = SM_SCALE + 512;     // 128 floats: pos arg (log2 units)
static constexpr int SM_RSA   = SM_POS + 512;       // 128 floats: col-half-0 row sums
static constexpr int SM_RSB   = SM_RSA + 512;       // 128 floats: col-half-1 row sums
static constexpr int SM_WRED  = SM_RSB + 512;       // 16 floats
static constexpr int SM_A     = 4096;               // 128x256 bf16, swizzled (64KB)
static constexpr int SM_B0    = SM_A + 65536;       // B chunk buf0 (64KB)
static constexpr int SM_B1    = SM_B0 + 65536;      // B chunk buf1 (64KB)
static constexpr int SM_TOTAL = SM_B1 + 65536;      // 200704 bytes

// ---------------- device scratch (no allocations allowed) ----------------
__device__ __nv_bfloat16 g_norm_dev[K_G * C_DIM];
__device__ float g_partial[NB];

// ---------------- helpers ----------------
DINLINE uint32_t smem_u32(const void* p) {
    uint32_t a;
    asm("{ .reg .u64 t; cvta.to.shared.u64 t, %1; cvt.u32.u64 %0, t; }" : "=r"(a) : "l"(p));
    return a;
}
#define SWZ(o) ((o) ^ (((o) >> 3) & 0x70))

// Address of element (row, col) in a 128x256-bf16 tile stored as four 16KB
// 64-col blocks, 128B rows, SW128-swizzled. col must be a multiple of 8.
DINLINE uint32_t tile_addr(uint32_t base, int row, int col) {
    uint32_t blk = (uint32_t)col >> 6;
    uint32_t g   = ((uint32_t)col & 63) >> 3;
    return base + (blk << 14) + SWZ(((uint32_t)row << 7) + (g << 4));
}

DINLINE void ldmatrix_x4(uint32_t& r0, uint32_t& r1, uint32_t& r2, uint32_t& r3, uint32_t addr) {
    asm volatile("ldmatrix.sync.aligned.m8n8.x4.shared.b16 {%0,%1,%2,%3}, [%4];"
                 : "=r"(r0), "=r"(r1), "=r"(r2), "=r"(r3) : "r"(addr));
}

DINLINE void mma_bf16(float& c0, float& c1, float& c2, float& c3,
                      uint32_t a0, uint32_t a1, uint32_t a2, uint32_t a3,
                      uint32_t b0, uint32_t b1) {
    asm volatile("mma.sync.aligned.m16n8k16.row.col.f32.bf16.bf16.f32 "
                 "{%0,%1,%2,%3}, {%4,%5,%6,%7}, {%8,%9}, {%0,%1,%2,%3};"
                 : "+f"(c0), "+f"(c1), "+f"(c2), "+f"(c3)
                 : "r"(a0), "r"(a1), "r"(a2), "r"(a3), "r"(b0), "r"(b1));
}

// cp.async a 128x256-bf16 G chunk into swizzled SMEM (one commit group)
DINLINE void load_b_chunk(uint32_t sb, int chunk, int tid) {
    uint32_t base = sb + ((chunk & 1) ? SM_B1 : SM_B0);
    const __nv_bfloat16* __restrict__ src = g_norm_dev + (size_t)chunk * (CHUNK_N * C_DIM);
#pragma unroll
    for (int i = 0; i < 8; i++) {
        int idx = i * NTHREADS + tid;        // 0..4095
        int r  = idx >> 5;                   // g row within chunk (0..127)
        int gc = idx & 31;                   // 16B granule within row (0..31)
        uint32_t off = ((uint32_t)(gc >> 3) << 14) + SWZ(((uint32_t)r << 7) + ((uint32_t)(gc & 7) << 4));
        uint32_t dst = base + off;
        const __nv_bfloat16* s = src + ((size_t)r << 8) + (gc << 3);
        asm volatile("cp.async.cg.shared.global [%0], [%1], 16;\n" :: "r"(dst), "l"(s) : "memory");
    }
    asm volatile("cp.async.commit_group;\n" ::: "memory");
}

// ---------------- kernel 1: normalize g -> bf16 ----------------
__global__ void prep_g_kernel(const float* __restrict__ g) {
    int row = blockIdx.x;     // 0..1023
    int t = threadIdx.x;      // 0..63
    const float4* gr = reinterpret_cast<const float4*>(g + (size_t)row * C_DIM);
    float4 v = gr[t];
    float ss = v.x * v.x + v.y * v.y + v.z * v.z + v.w * v.w;
#pragma unroll
    for (int o = 16; o > 0; o >>= 1) ss += __shfl_xor_sync(0xffffffffu, ss, o);
    __shared__ float w2[2];
    if ((t & 31) == 0) w2[t >> 5] = ss;
    __syncthreads();
    float inv = rsqrtf(w2[0] + w2[1]);
    __nv_bfloat16* out = g_norm_dev + (size_t)row * C_DIM + t * 4;
    out[0] = __float2bfloat16(v.x * inv);
    out[1] = __float2bfloat16(v.y * inv);
    out[2] = __float2bfloat16(v.z * inv);
    out[3] = __float2bfloat16(v.w * inv);
}

// ---------------- kernel 2: main fused GEMM + softmax-denominator ----------------
__global__ void __launch_bounds__(NTHREADS, 1) main_kernel(const float* __restrict__ l) {
    extern __shared__ char smem[];
    uint32_t sb = smem_u32(smem);
    int tid  = threadIdx.x;
    int wid  = tid >> 5;          // 0..15
    int lane = tid & 31;
    int warpRow  = (wid & 7) * 16;   // 16 rows per warp
    int colHalf  = wid >> 3;         // cols [colHalf*64, +64) of each chunk
    int b = blockIdx.x;              // batch index; positive g index == b

    float* scale_p = reinterpret_cast<float*>(smem + SM_SCALE);
    float* pos_p   = reinterpret_cast<float*>(smem + SM_POS);
    float* rsA     = reinterpret_cast<float*>(smem + SM_RSA);
    float* rsB     = reinterpret_cast<float*>(smem + SM_RSB);
    float* wred    = reinterpret_cast<float*>(smem + SM_WRED);

    // kick off G chunk0+1 loads first (overlap the L-tile prologue)
    load_b_chunk(sb, 0, tid);
    load_b_chunk(sb, 1, tid);

    // ---- load L tile (fp32), convert to swizzled bf16 A, compute row sumsq ----
    const float* __restrict__ lbase = l + (size_t)b * TILE_M * C_DIM;
#pragma unroll
    for (int i = 0; i < 8; i++) {
        int row = i * 16 + wid;      // whole warp covers one row
        int gc  = lane;              // 8-float granule
        const float4* p = reinterpret_cast<const float4*>(lbase + (size_t)row * C_DIM + gc * 8);
        float4 a = p[0];
        float4 c = p[1];
        float ss = a.x*a.x + a.y*a.y + a.z*a.z + a.w*a.w +
                   c.x*c.x + c.y*c.y + c.z*c.z + c.w*c.w;
#pragma unroll
        for (int o = 16; o > 0; o >>= 1) ss += __shfl_xor_sync(0xffffffffu, ss, o);
        if (lane == 0) scale_p[row] = ss;
        __nv_bfloat162 p0 = __floats2bfloat162_rn(a.x, a.y);
        __nv_bfloat162 p1 = __floats2bfloat162_rn(a.z, a.w);
        __nv_bfloat162 p2 = __floats2bfloat162_rn(c.x, c.y);
        __nv_bfloat162 p3 = __floats2bfloat162_rn(c.z, c.w);
        uint4 u;
        u.x = *reinterpret_cast<uint32_t*>(&p0);
        u.y = *reinterpret_cast<uint32_t*>(&p1);
        u.z = *reinterpret_cast<uint32_t*>(&p2);
        u.w = *reinterpret_cast<uint32_t*>(&p3);
        uint32_t off = ((uint32_t)(gc >> 3) << 14) + SWZ(((uint32_t)row << 7) + ((uint32_t)(gc & 7) << 4));
        *reinterpret_cast<uint4*>(smem + SM_A + off) = u;
    }
    __syncthreads();
    if (tid < 128) {
        // scale = 1/(|l| * T * ln2): args in log2 units -> raw EX2 in epilogue
        scale_p[tid] = rsqrtf(scale_p[tid]) * (5.0f * 1.44269504088896f);
    }
    __syncthreads();

    float sc0 = scale_p[warpRow + (lane >> 2)];
    float sc1 = scale_p[warpRow + (lane >> 2) + 8];
    int r0 = warpRow + (lane >> 2);

    // positive column decomposition
    int pchunk = b >> 7;
    int pcol   = b & 127;
    int ph     = pcol >> 6;             // col half
    int pj     = (pcol & 63) >> 3;      // n-tile within half
    int ppair  = ((pcol & 63) >> 1) & 3;// lane%4 slot
    int psel   = pcol & 1;              // element within pair

    // fragment address components (fixed per thread)
    int a_row  = warpRow + (lane & 15);
    int a_koff = (lane >> 4) * 8;
    int b_nrow = colHalf * 64 + (lane & 7) + ((lane >> 4) << 3);
    int b_koff = ((lane >> 3) & 1) * 8;

    float acc[8][4];
#pragma unroll
    for (int j = 0; j < 8; j++)
#pragma unroll
        for (int e = 0; e < 4; e++) acc[j][e] = 0.0f;

    float rs0 = 0.0f, rs1 = 0.0f;

    for (int c = 0; c < NCHUNK; c++) {
        if (c < NCHUNK - 1) asm volatile("cp.async.wait_group 1;" ::: "memory");
        else                asm volatile("cp.async.wait_group 0;" ::: "memory");
        __syncthreads();

        uint32_t bbase = sb + ((c & 1) ? SM_B1 : SM_B0);

        // ---- GEMM: 16 k-steps over C=256 ----
#pragma unroll
        for (int ks = 0; ks < NKSTEP; ks++) {
            int kc = ks * 16;
            uint32_t a0, a1, a2, a3;
            ldmatrix_x4(a0, a1, a2, a3, tile_addr(sb + SM_A, a_row, kc + a_koff));
#pragma unroll
            for (int t = 0; t < 4; t++) {
                uint32_t b0, b1, b2, b3;
                ldmatrix_x4(b0, b1, b2, b3, tile_addr(bbase, b_nrow + t * 16, kc + b_koff));
                float* cA = acc[t * 2];
                float* cB = acc[t * 2 + 1];
                mma_bf16(cA[0], cA[1], cA[2], cA[3], a0, a1, a2, a3, b0, b1);
                mma_bf16(cB[0], cB[1], cB[2], cB[3], a0, a1, a2, a3, b2, b3);
            }
        }

        __syncthreads();                       // all warps done reading B buf c&1
        if (c + 2 < NCHUNK) load_b_chunk(sb, c + 2, tid);

        // ---- epilogue: capture positive, exp2, row-sum, zero accums ----
        if (c == pchunk && colHalf == ph && (lane & 3) == ppair) {
            pos_p[r0]     = acc[pj][psel]     * sc0;
            pos_p[r0 + 8] = acc[pj][2 + psel] * sc1;
        }
#pragma unroll
        for (int j = 0; j < 8; j++) {
#pragma unroll
            for (int e = 0; e < 4; e++) {
                float arg = acc[j][e] * ((e < 2) ? sc0 : sc1);
                float ex;
                asm("ex2.approx.ftz.f32 %0, %1;" : "=f"(ex) : "f"(arg));
                if (e < 2) rs0 += ex; else rs1 += ex;
                acc[j][e] = 0.0f;
            }
        }
    }

    // ---- reduce row sums across the 4-lane column groups ----
    rs0 += __shfl_xor_sync(0xffffffffu, rs0, 1);
    rs0 += __shfl_xor_sync(0xffffffffu, rs0, 2);
    rs1 += __shfl_xor_sync(0xffffffffu, rs1, 1);
    rs1 += __shfl_xor_sync(0xffffffffu, rs1, 2);
    if ((lane & 3) == 0) {
        float* dst = colHalf ? rsB : rsA;
        dst[r0]     = rs0;
        dst[r0 + 8] = rs1;
    }
    __syncthreads();

    // ---- per-row loss, CTA reduce ----
    float loss = 0.0f;
    if (tid < 128) {
        float tot = rsA[tid] + rsB[tid];
        float pa = pos_p[tid];          // log2 units
        float ep;
        asm("ex2.approx.ftz.f32 %0, %1;" : "=f"(ep) : "f"(pa));
        float denom = tot - ep;
        loss = logf(denom) - pa * 0.693147180559945f;
    }
#pragma unroll
    for (int o = 16; o > 0; o >>= 1) loss += __shfl_xor_sync(0xffffffffu, loss, o);
    if (lane == 0) wred[wid] = loss;
    __syncthreads();
    if (tid == 0) {
        float s = 0.0f;
#pragma unroll
        for (int i = 0; i < 16; i++) s += wred[i];
        g_partial[b] = s;
    }
}

// ---------------- kernel 3: final reduction ----------------
__global__ void reduce_kernel(float* __restrict__ out) {
    __shared__ float ws[8];
    int tid = threadIdx.x;  // 256
    float s = 0.0f;
#pragma unroll
    for (int i = 0; i < 4; i++) s += g_partial[tid + i * 256];
#pragma unroll
    for (int o = 16; o > 0; o >>= 1) s += __shfl_xor_sync(0xffffffffu, s, o);
    if ((tid & 31) == 0) ws[tid >> 5] = s;
    __syncthreads();
    if (tid == 0) {
        float t = 0.0f;
#pragma unroll
        for (int i = 0; i < 8; i++) t += ws[i];
        out[0] = t * (1.0f / 131072.0f);
    }
}

// ---------------- launch ----------------
extern "C" void kernel_launch(void* const* d_in, const int* in_sizes, int n_in,
                              void* d_out, int out_size) {
    const float* l = (const float*)d_in[0];
    const float* g = (const float*)d_in[1];
    if (n_in >= 2 && in_sizes[0] < in_sizes[1]) {  // defensive: l_enc is the big one
        const float* t = l; l = g; g = t;
    }
    cudaFuncSetAttribute(main_kernel, cudaFuncAttributeMaxDynamicSharedMemorySize, SM_TOTAL);
    prep_g_kernel<<<K_G, 64>>>(g);
    main_kernel<<<NB, NTHREADS, SM_TOTAL>>>(l);
    reduce_kernel<<<1, 256>>>((float*)d_out);
}